// round 1
// baseline (speedup 1.0000x reference)
#include <cuda_runtime.h>

// Two fused SAME-padded 3x3 single-channel convs:
//   y = conv3x3(x, w1)  (zero pad, y forced to 0 outside image)
//   z = conv3x3(y, w2)  (zero pad)
// x: [B,1,2048,2048] fp32, w1/w2: 9 floats each (cross-correlation, no flip).

#define IMG_H 2048
#define IMG_W 2048
#define TH 64          // output tile height per block
#define TW 128         // output tile width per block
#define XH 72          // x smem rows   (TH + 4 halo + 4 pad for uniform 4-row groups)
#define XW 136         // smem row stride (TW + 8), also loaded width
#define SYH 68         // y smem rows (s = global_row - (r0-1), s in [0,67], z uses [0,65])
#define NTHREADS 256

__global__ __launch_bounds__(NTHREADS, 3)
void conv2x_fused_kernel(const float* __restrict__ x,
                         const float* __restrict__ w1g,
                         const float* __restrict__ w2g,
                         float* __restrict__ out)
{
    extern __shared__ float smem[];
    float* sx = smem;                 // XH * XW   : sx[r][cx] = x[r0-2+r][c0-2+cx] (0 outside)
    float* sy = smem + XH * XW;       // SYH * XW  : sy[s][c'] = y[r0-1+s][c0-1+c'] (0 outside img)

    const int tid = threadIdx.x;
    const int c0  = blockIdx.x * TW;
    const int r0  = blockIdx.y * TH;
    const int bz  = blockIdx.z;

    float w1[9], w2[9];
#pragma unroll
    for (int i = 0; i < 9; i++) { w1[i] = __ldg(&w1g[i]); w2[i] = __ldg(&w2g[i]); }

    const float* xb = x + (size_t)bz * IMG_H * IMG_W;

    // ---- Phase 0: load x tile (with zero padding outside image) ----
    for (int idx = tid; idx < XH * XW; idx += NTHREADS) {
        int r  = idx / XW;
        int cx = idx - r * XW;
        int gr = r0 - 2 + r;
        int gc = c0 - 2 + cx;
        float v = 0.0f;
        if (gr >= 0 && gr < IMG_H && gc >= 0 && gc < IMG_W)
            v = __ldg(&xb[(size_t)gr * IMG_W + gc]);
        sx[idx] = v;
    }
    __syncthreads();

    // ---- Phase 1: y = conv(x, w1), 4x4 micro-tiles, float4 LDS ----
    // y row s needs sx rows s..s+2; row groups u=0..16 cover s=0..67 (sx rows up to 69 < 72).
    // col groups g=0..32 cover c'=0..131 (sx cols up to 133+padload..135).
    for (int t = tid; t < 17 * 33; t += NTHREADS) {
        int u = t / 33;
        int g = t - u * 33;
        int s0  = 4 * u;
        int cp0 = 4 * g;
        float acc[4][4] = {};
#pragma unroll
        for (int xr = 0; xr < 6; xr++) {
            int r = s0 + xr;
            float4 v0 = *(const float4*)&sx[r * XW + cp0];
            float4 v1 = *(const float4*)&sx[r * XW + cp0 + 4];
            float xv[8] = {v0.x, v0.y, v0.z, v0.w, v1.x, v1.y, v1.z, v1.w};
#pragma unroll
            for (int i = 0; i < 4; i++) {
                if (i < xr - 2 || i > xr) continue;   // compile-time pruned
                int a = xr - i;
#pragma unroll
                for (int j = 0; j < 4; j++)
#pragma unroll
                    for (int b = 0; b < 3; b++)
                        acc[i][j] = fmaf(w1[a * 3 + b], xv[j + b], acc[i][j]);
            }
        }
        // mask y to zero outside the image (second conv pads y with zeros), store
#pragma unroll
        for (int i = 0; i < 4; i++) {
            int s  = s0 + i;
            int gr = r0 - 1 + s;
            bool rok = (gr >= 0) && (gr < IMG_H);
            float4 o;
            float* op = (float*)&o;
#pragma unroll
            for (int j = 0; j < 4; j++) {
                int gc = c0 - 1 + cp0 + j;
                op[j] = (rok && gc >= 0 && gc < IMG_W) ? acc[i][j] : 0.0f;
            }
            *(float4*)&sy[s * XW + cp0] = o;
        }
    }
    __syncthreads();

    // ---- Phase 2: z = conv(y, w2), 4x4 micro-tiles, float4 LDS, float4 STG ----
    float* ob = out + (size_t)bz * IMG_H * IMG_W;
    for (int t = tid; t < 16 * 32; t += NTHREADS) {
        int u = t >> 5;          // / 32
        int g = t & 31;          // % 32
        int zr0 = 4 * u;
        int zc0 = 4 * g;
        float acc[4][4] = {};
#pragma unroll
        for (int yr = 0; yr < 6; yr++) {
            int s = zr0 + yr;    // max 65 < 68
            float4 v0 = *(const float4*)&sy[s * XW + zc0];
            float4 v1 = *(const float4*)&sy[s * XW + zc0 + 4];
            float yv[8] = {v0.x, v0.y, v0.z, v0.w, v1.x, v1.y, v1.z, v1.w};
#pragma unroll
            for (int i = 0; i < 4; i++) {
                if (i < yr - 2 || i > yr) continue;
                int a = yr - i;
#pragma unroll
                for (int j = 0; j < 4; j++)
#pragma unroll
                    for (int b = 0; b < 3; b++)
                        acc[i][j] = fmaf(w2[a * 3 + b], yv[j + b], acc[i][j]);
            }
        }
#pragma unroll
        for (int i = 0; i < 4; i++) {
            size_t o = (size_t)(r0 + zr0 + i) * IMG_W + (c0 + zc0);
            *(float4*)&ob[o] = make_float4(acc[i][0], acc[i][1], acc[i][2], acc[i][3]);
        }
    }
}

extern "C" void kernel_launch(void* const* d_in, const int* in_sizes, int n_in,
                              void* d_out, int out_size)
{
    const float* x  = (const float*)d_in[0];
    const float* w1 = (const float*)d_in[1];
    const float* w2 = (const float*)d_in[2];
    float* out = (float*)d_out;

    const int B = in_sizes[0] / (IMG_H * IMG_W);   // 16
    const int smem_bytes = (XH * XW + SYH * XW) * (int)sizeof(float);  // 76160

    cudaFuncSetAttribute(conv2x_fused_kernel,
                         cudaFuncAttributeMaxDynamicSharedMemorySize, smem_bytes);

    dim3 grid(IMG_W / TW, IMG_H / TH, B);   // 16 x 32 x 16
    conv2x_fused_kernel<<<grid, NTHREADS, smem_bytes>>>(x, w1, w2, out);
}

// round 2
// speedup vs baseline: 1.0253x; 1.0253x over previous
#include <cuda_runtime.h>

// Fused: y = conv3x3_same(x, w1) ; z = conv3x3_same(y, w2)
// x: [B,1,2048,2048] fp32; w1,w2: 3x3 (cross-correlation, zero pad).
// y is computed in smem and explicitly zeroed outside the image (matches
// two sequential SAME convs exactly, which differ from one 5x5 at borders).

#define IMG_H 2048
#define IMG_W 2048
#define TH 64          // output rows per block
#define TW 128         // output cols per block
#define XH 68          // sx rows: x[r0-2 .. r0+65]
#define XW 136         // sx/sy col stride; sx cols: x[c0-4 .. c0+131]
#define SYH 66         // sy rows: y[r0-1 .. r0+64]  (sIdx = gr-(r0-1))
#define NTHREADS 256
#define N4LOAD (XH * (XW / 4))     // 2312 float4

// Phase 1: y = conv(x, w1). 17x17 groups of 4row x 8col micro-tiles.
// sy[s][c] = y[r0-1+s][c0-1+c]; needs sx cols (c+2 .. c+4) under the -4 shift.
template <bool MASK>
__device__ __forceinline__ void phase1(const float* __restrict__ sx,
                                       float* __restrict__ sy,
                                       const float* w1, int r0, int c0, int tid)
{
    for (int t = tid; t < 17 * 17; t += NTHREADS) {
        int u = t / 17;
        int g = t - u * 17;
        int s0  = (u == 16) ? 62 : 4 * u;     // clamp: rows 62..65 overlap (same values)
        int cp0 = (g == 16) ? 124 : 8 * g;    // clamp: cols 124..131 overlap (same values)
        float acc[4][8];
#pragma unroll
        for (int i = 0; i < 4; i++)
#pragma unroll
            for (int j = 0; j < 8; j++) acc[i][j] = 0.0f;

#pragma unroll
        for (int xr = 0; xr < 6; xr++) {
            const float* row = sx + (s0 + xr) * XW + cp0;
            float4 a0 = *(const float4*)(row);
            float4 a1 = *(const float4*)(row + 4);
            float4 a2 = *(const float4*)(row + 8);
            float xv[12] = {a0.x, a0.y, a0.z, a0.w,
                            a1.x, a1.y, a1.z, a1.w,
                            a2.x, a2.y, a2.z, a2.w};
#pragma unroll
            for (int i = 0; i < 4; i++) {
                if (i >= xr - 2 && i <= xr) {      // compile-time pruned
                    int a = xr - i;
#pragma unroll
                    for (int j = 0; j < 8; j++)
#pragma unroll
                        for (int b = 0; b < 3; b++)
                            acc[i][j] = fmaf(w1[a * 3 + b], xv[j + 2 + b], acc[i][j]);
                }
            }
        }
#pragma unroll
        for (int i = 0; i < 4; i++) {
            if (MASK) {
                int gr = r0 - 1 + s0 + i;
                bool rok = ((unsigned)gr < IMG_H);
#pragma unroll
                for (int j = 0; j < 8; j++) {
                    int gc = c0 - 1 + cp0 + j;
                    if (!rok || (unsigned)gc >= IMG_W) acc[i][j] = 0.0f;
                }
            }
            float* dst = sy + (s0 + i) * XW + cp0;
            *(float4*)(dst)     = make_float4(acc[i][0], acc[i][1], acc[i][2], acc[i][3]);
            *(float4*)(dst + 4) = make_float4(acc[i][4], acc[i][5], acc[i][6], acc[i][7]);
        }
    }
}

__global__ __launch_bounds__(NTHREADS, 3)
void conv2x_fused(const float* __restrict__ x, const float* __restrict__ w1g,
                  const float* __restrict__ w2g, float* __restrict__ out)
{
    extern __shared__ float smem[];
    float* sx = smem;                 // XH * XW
    float* sy = smem + XH * XW;       // SYH * XW

    const int tid = threadIdx.x;
    const int c0  = blockIdx.x * TW;
    const int r0  = blockIdx.y * TH;
    const float* xb = x   + (size_t)blockIdx.z * ((size_t)IMG_H * IMG_W);
    float*       ob = out + (size_t)blockIdx.z * ((size_t)IMG_H * IMG_W);

    float w1[9], w2[9];
#pragma unroll
    for (int i = 0; i < 9; i++) { w1[i] = __ldg(w1g + i); w2[i] = __ldg(w2g + i); }

    const bool interior = (blockIdx.x != 0) && (blockIdx.x != gridDim.x - 1) &&
                          (blockIdx.y != 0) && (blockIdx.y != gridDim.y - 1);

    // ---- Phase 0: x tile -> smem ----
    if (interior) {
        // All rows/cols in-image; float4 everywhere. sx[r][c4] = x[r0-2+r][c0-4+4*c4..]
        const float4* xg = (const float4*)(xb + (size_t)(r0 - 2) * IMG_W + (c0 - 4));
        float4* sx4 = (float4*)sx;
        float4 tmp[10];
        int    ok[10];
#pragma unroll
        for (int k = 0; k < 10; k++) {
            int i = tid + k * NTHREADS;
            ok[k] = (i < N4LOAD);
            if (ok[k]) {
                int r = i / (XW / 4);
                int c = i - r * (XW / 4);
                tmp[k] = xg[(size_t)r * (IMG_W / 4) + c];
            }
        }
#pragma unroll
        for (int k = 0; k < 10; k++) {
            int i = tid + k * NTHREADS;
            if (ok[k]) sx4[i] = tmp[k];
        }
    } else {
        for (int i = tid; i < XH * XW; i += NTHREADS) {
            int r = i / XW;
            int c = i - r * XW;
            int gr = r0 - 2 + r;
            int gc = c0 - 4 + c;
            float v = 0.0f;
            if ((unsigned)gr < IMG_H && (unsigned)gc < IMG_W)
                v = __ldg(xb + (size_t)gr * IMG_W + gc);
            sx[i] = v;
        }
    }
    __syncthreads();

    // ---- Phase 1: y -> smem ----
    if (interior) phase1<false>(sx, sy, w1, r0, c0, tid);
    else          phase1<true >(sx, sy, w1, r0, c0, tid);
    __syncthreads();

    // ---- Phase 2: z = conv(y, w2); exactly one 4x8 micro-tile per thread ----
    {
        const int u = tid >> 4;         // 16 row groups
        const int g = tid & 15;         // 16 col groups
        const int zr0 = 4 * u;
        const int zc0 = 8 * g;
        float acc[4][8];
#pragma unroll
        for (int i = 0; i < 4; i++)
#pragma unroll
            for (int j = 0; j < 8; j++) acc[i][j] = 0.0f;

#pragma unroll
        for (int yr = 0; yr < 6; yr++) {
            const float* row = sy + (zr0 + yr) * XW + zc0;
            float4 a0 = *(const float4*)(row);
            float4 a1 = *(const float4*)(row + 4);
            float4 a2 = *(const float4*)(row + 8);
            float yv[12] = {a0.x, a0.y, a0.z, a0.w,
                            a1.x, a1.y, a1.z, a1.w,
                            a2.x, a2.y, a2.z, a2.w};
#pragma unroll
            for (int i = 0; i < 4; i++) {
                if (i >= yr - 2 && i <= yr) {
                    int a = yr - i;
#pragma unroll
                    for (int j = 0; j < 8; j++)
#pragma unroll
                        for (int b = 0; b < 3; b++)
                            acc[i][j] = fmaf(w2[a * 3 + b], yv[j + b], acc[i][j]);
                }
            }
        }
#pragma unroll
        for (int i = 0; i < 4; i++) {
            float* dst = ob + (size_t)(r0 + zr0 + i) * IMG_W + (c0 + zc0);
            *(float4*)(dst)     = make_float4(acc[i][0], acc[i][1], acc[i][2], acc[i][3]);
            *(float4*)(dst + 4) = make_float4(acc[i][4], acc[i][5], acc[i][6], acc[i][7]);
        }
    }
}

extern "C" void kernel_launch(void* const* d_in, const int* in_sizes, int n_in,
                              void* d_out, int out_size)
{
    const float* x  = (const float*)d_in[0];
    const float* w1 = (const float*)d_in[1];
    const float* w2 = (const float*)d_in[2];
    float* out = (float*)d_out;

    const int B = in_sizes[0] / (IMG_H * IMG_W);     // 16
    const int smem_bytes = (XH * XW + SYH * XW) * (int)sizeof(float);  // 72896

    cudaFuncSetAttribute(conv2x_fused,
                         cudaFuncAttributeMaxDynamicSharedMemorySize, smem_bytes);

    dim3 grid(IMG_W / TW, IMG_H / TH, B);            // 16 x 32 x 16
    conv2x_fused<<<grid, NTHREADS, smem_bytes>>>(x, w1, w2, out);
}

// round 3
// speedup vs baseline: 1.1851x; 1.1559x over previous
#include <cuda_runtime.h>

// Fused: y = conv3x3_same(x, w1) ; z = conv3x3_same(y, w2)
// x: [B,1,2048,2048] fp32; w1,w2: 3x3 (cross-correlation, zero pad).
// y lives in smem, explicitly zeroed outside the image (two sequential SAME
// convs differ from one 5x5 at borders).
//
// Key layout rule: all micro-tiles are 4 columns wide and consecutive threads
// take consecutive column groups, so every LDS.128 / STS.128 / STG.128
// wavefront touches 32 distinct banks (conflict-free).

#define IMG_H 2048
#define IMG_W 2048
#define TH 64          // output rows per block
#define TW 128         // output cols per block
#define XH 68          // sx rows: x[r0-2 .. r0+65]
#define XW 136         // col stride; sx cols: x[c0-4 .. c0+131]
#define XW4 (XW / 4)   // 34
#define SYH 66         // sy rows: y[r0-1 .. r0+64]
#define NTHREADS 512
#define N4LOAD (XH * XW4)   // 2312 float4

__device__ __forceinline__ void cp_async16(void* sdst, const void* gsrc)
{
    unsigned s = (unsigned)__cvta_generic_to_shared(sdst);
    asm volatile("cp.async.cg.shared.global [%0], [%1], 16;" :: "r"(s), "l"(gsrc));
}

// One phase-1 item: 4 rows x 4 cols of y -> smem.
// sy[s][c] = y[r0-1+s][c0-1+c]; x col (c-1+b) sits at sx col c+2+b (-4 shift).
template <bool MASK>
__device__ __forceinline__ void p1_item(int t, const float* __restrict__ sx,
                                        float* __restrict__ sy,
                                        const float* w1, int r0, int c0)
{
    int u = t / 33;
    int g = t - u * 33;
    int s0  = (u == 16) ? 62 : 4 * u;   // rows 62..63 double-written with identical values
    int cp0 = 4 * g;                    // 33 groups cover sy cols 0..131 exactly
    float acc[4][4] = {};
#pragma unroll
    for (int xr = 0; xr < 6; xr++) {
        const float* row = sx + (s0 + xr) * XW + cp0;
        float4 a0 = *(const float4*)(row);
        float4 a1 = *(const float4*)(row + 4);
        float xv[8] = {a0.x, a0.y, a0.z, a0.w, a1.x, a1.y, a1.z, a1.w};
#pragma unroll
        for (int i = 0; i < 4; i++) {
            if (i >= xr - 2 && i <= xr) {          // compile-time pruned
                int a = xr - i;
#pragma unroll
                for (int j = 0; j < 4; j++)
#pragma unroll
                    for (int b = 0; b < 3; b++)
                        acc[i][j] = fmaf(w1[a * 3 + b], xv[2 + j + b], acc[i][j]);
            }
        }
    }
#pragma unroll
    for (int i = 0; i < 4; i++) {
        if (MASK) {
            int gr = r0 - 1 + s0 + i;
            bool rok = ((unsigned)gr < IMG_H);
#pragma unroll
            for (int j = 0; j < 4; j++) {
                int gc = c0 - 1 + cp0 + j;
                if (!rok || (unsigned)gc >= IMG_W) acc[i][j] = 0.0f;
            }
        }
        *(float4*)(sy + (s0 + i) * XW + cp0) =
            make_float4(acc[i][0], acc[i][1], acc[i][2], acc[i][3]);
    }
}

__global__ __launch_bounds__(NTHREADS, 2)
void conv2x_fused(const float* __restrict__ x, const float* __restrict__ w1g,
                  const float* __restrict__ w2g, float* __restrict__ out)
{
    extern __shared__ float smem[];
    float* sx = smem;                 // XH * XW
    float* sy = smem + XH * XW;       // SYH * XW

    const int tid = threadIdx.x;
    const int c0  = blockIdx.x * TW;
    const int r0  = blockIdx.y * TH;
    const float* xb = x   + (size_t)blockIdx.z * ((size_t)IMG_H * IMG_W);
    float*       ob = out + (size_t)blockIdx.z * ((size_t)IMG_H * IMG_W);

    float w1[9], w2[9];
#pragma unroll
    for (int i = 0; i < 9; i++) { w1[i] = __ldg(w1g + i); w2[i] = __ldg(w2g + i); }

    const bool interior = (blockIdx.x != 0) && (blockIdx.x != gridDim.x - 1) &&
                          (blockIdx.y != 0) && (blockIdx.y != gridDim.y - 1);

    // ---- Phase 0: x tile -> smem ----
    if (interior) {
        const float4* xg = (const float4*)(xb + (size_t)(r0 - 2) * IMG_W + (c0 - 4));
        float4* sx4 = (float4*)sx;
#pragma unroll
        for (int k = 0; k < 5; k++) {
            int i = tid + k * NTHREADS;
            if (i < N4LOAD) {
                int r = i / XW4;
                int c = i - r * XW4;
                cp_async16(sx4 + i, xg + (size_t)r * (IMG_W / 4) + c);
            }
        }
        asm volatile("cp.async.commit_group;");
        asm volatile("cp.async.wait_group 0;");
    } else {
        for (int i = tid; i < XH * XW; i += NTHREADS) {
            int r = i / XW;
            int c = i - r * XW;
            int gr = r0 - 2 + r;
            int gc = c0 - 4 + c;
            float v = 0.0f;
            if ((unsigned)gr < IMG_H && (unsigned)gc < IMG_W)
                v = __ldg(xb + (size_t)gr * IMG_W + gc);
            sx[i] = v;
        }
    }
    __syncthreads();

    // ---- Phase 1: y -> smem (561 items over 512 threads) ----
    if (interior) {
        p1_item<false>(tid, sx, sy, w1, r0, c0);
        if (tid < 17 * 33 - NTHREADS) p1_item<false>(tid + NTHREADS, sx, sy, w1, r0, c0);
    } else {
        p1_item<true>(tid, sx, sy, w1, r0, c0);
        if (tid < 17 * 33 - NTHREADS) p1_item<true>(tid + NTHREADS, sx, sy, w1, r0, c0);
    }
    __syncthreads();

    // ---- Phase 2: z = conv(y, w2); exactly one 4x4 tile per thread ----
    {
        const int u = tid >> 5;          // 16 row groups
        const int g = tid & 31;          // 32 col groups (consecutive lanes -> consecutive 16B)
        const int zr0 = 4 * u;
        const int zc0 = 4 * g;
        float acc[4][4] = {};
#pragma unroll
        for (int yr = 0; yr < 6; yr++) {
            const float* row = sy + (zr0 + yr) * XW + zc0;
            float4 a0 = *(const float4*)(row);
            float4 a1 = *(const float4*)(row + 4);
            float yv[8] = {a0.x, a0.y, a0.z, a0.w, a1.x, a1.y, a1.z, a1.w};
#pragma unroll
            for (int i = 0; i < 4; i++) {
                if (i >= yr - 2 && i <= yr) {
                    int a = yr - i;
#pragma unroll
                    for (int j = 0; j < 4; j++)
#pragma unroll
                        for (int b = 0; b < 3; b++)
                            acc[i][j] = fmaf(w2[a * 3 + b], yv[j + b], acc[i][j]);
                }
            }
        }
#pragma unroll
        for (int i = 0; i < 4; i++) {
            float* dst = ob + (size_t)(r0 + zr0 + i) * IMG_W + (c0 + zc0);
            *(float4*)dst = make_float4(acc[i][0], acc[i][1], acc[i][2], acc[i][3]);
        }
    }
}

extern "C" void kernel_launch(void* const* d_in, const int* in_sizes, int n_in,
                              void* d_out, int out_size)
{
    const float* x  = (const float*)d_in[0];
    const float* w1 = (const float*)d_in[1];
    const float* w2 = (const float*)d_in[2];
    float* out = (float*)d_out;

    const int B = in_sizes[0] / (IMG_H * IMG_W);     // 16
    const int smem_bytes = (XH * XW + SYH * XW) * (int)sizeof(float);  // 72896

    cudaFuncSetAttribute(conv2x_fused,
                         cudaFuncAttributeMaxDynamicSharedMemorySize, smem_bytes);

    dim3 grid(IMG_W / TW, IMG_H / TH, B);            // 16 x 32 x 16
    conv2x_fused<<<grid, NTHREADS, smem_bytes>>>(x, w1, w2, out);
}

// round 4
// speedup vs baseline: 1.5492x; 1.3072x over previous
#include <cuda_runtime.h>

// Fused y = conv3x3_same(x, w1); z = conv3x3_same(y, w2) for [16,1,2048,2048] fp32.
// Register-streaming: no shared memory, no barriers. Each warp owns a
// 128-col x 64-row chunk; lane g owns 4 cols. Horizontal halos via warp
// shuffles; warp-edge halo column computed by lanes 0/31 from a small extra
// load. y is forced to 0 outside the image (exact two-pass SAME semantics).

#define IMG_H 2048
#define IMG_W 2048
#define ROWS_PER_WARP 64
#define STRIPS 16          // 2048 / 128
#define WARPS_PER_CTA 4

struct XR { float v0, v1, v2, v3, xm1, xp4, ea, ec; };
struct YR { float y0, y1, y2, y3, ym1, yp4; };

__device__ __forceinline__ XR load_xrow(const float* __restrict__ xb, int row,
                                        int c0, int lane, bool lE, bool rE)
{
    XR r = {0.f,0.f,0.f,0.f,0.f,0.f,0.f,0.f};
    float h0 = 0.f, h1 = 0.f;
    if ((unsigned)row < IMG_H) {
        const float* base = xb + (size_t)row * IMG_W + c0;
        float4 v = __ldg((const float4*)(base + 4 * lane));
        r.v0 = v.x; r.v1 = v.y; r.v2 = v.z; r.v3 = v.w;
        if (lane == 0 && !lE)  { float2 h = __ldg((const float2*)(base - 2));   h0 = h.x; h1 = h.y; }
        if (lane == 31 && !rE) { float2 h = __ldg((const float2*)(base + 128)); h0 = h.x; h1 = h.y; }
    }
    float up = __shfl_up_sync(0xffffffffu, r.v3, 1);
    float dn = __shfl_down_sync(0xffffffffu, r.v0, 1);
    r.xm1 = (lane == 0)  ? h1 : up;     // x[c-1]
    r.xp4 = (lane == 31) ? h0 : dn;     // x[c+4]
    r.ea  = (lane == 0)  ? h0 : r.v3;   // edge col: x[c0-2] / x[c0+127]
    r.ec  = (lane == 0)  ? r.v0 : h1;   //           x[c0]   / x[c0+129]
    return r;
}

__device__ __forceinline__ void acc3(const XR& r, float wa, float wb, float wc,
                                     float& a0, float& a1, float& a2, float& a3,
                                     float& ae, int lane)
{
    a0 = fmaf(wa, r.xm1, a0); a0 = fmaf(wb, r.v0, a0); a0 = fmaf(wc, r.v1, a0);
    a1 = fmaf(wa, r.v0,  a1); a1 = fmaf(wb, r.v1, a1); a1 = fmaf(wc, r.v2, a1);
    a2 = fmaf(wa, r.v1,  a2); a2 = fmaf(wb, r.v2, a2); a2 = fmaf(wc, r.v3, a2);
    a3 = fmaf(wa, r.v2,  a3); a3 = fmaf(wb, r.v3, a3); a3 = fmaf(wc, r.xp4, a3);
    float eb = (lane == 0) ? r.xm1 : r.xp4;
    ae = fmaf(wa, r.ea, ae); ae = fmaf(wb, eb, ae); ae = fmaf(wc, r.ec, ae);
}

__device__ __forceinline__ YR compute_y(const XR& a, const XR& b, const XR& c,
                                        const float* w, bool valid, int lane,
                                        bool killE)
{
    float y0 = 0.f, y1 = 0.f, y2 = 0.f, y3 = 0.f, ye = 0.f;
    acc3(a, w[0], w[1], w[2], y0, y1, y2, y3, ye, lane);
    acc3(b, w[3], w[4], w[5], y0, y1, y2, y3, ye, lane);
    acc3(c, w[6], w[7], w[8], y0, y1, y2, y3, ye, lane);
    if (!valid) { y0 = y1 = y2 = y3 = ye = 0.f; }   // warp-uniform
    if (killE) ye = 0.f;                            // y zero-pad outside image cols
    YR o; o.y0 = y0; o.y1 = y1; o.y2 = y2; o.y3 = y3;
    float up = __shfl_up_sync(0xffffffffu, y3, 1);
    float dn = __shfl_down_sync(0xffffffffu, y0, 1);
    o.ym1 = (lane == 0)  ? ye : up;
    o.yp4 = (lane == 31) ? ye : dn;
    return o;
}

__device__ __forceinline__ void zrow(const YR& r, float wa, float wb, float wc,
                                     float& z0, float& z1, float& z2, float& z3)
{
    z0 = fmaf(wa, r.ym1, z0); z0 = fmaf(wb, r.y0, z0); z0 = fmaf(wc, r.y1, z0);
    z1 = fmaf(wa, r.y0,  z1); z1 = fmaf(wb, r.y1, z1); z1 = fmaf(wc, r.y2, z1);
    z2 = fmaf(wa, r.y1,  z2); z2 = fmaf(wb, r.y2, z2); z2 = fmaf(wc, r.y3, z2);
    z3 = fmaf(wa, r.y2,  z3); z3 = fmaf(wb, r.y3, z3); z3 = fmaf(wc, r.yp4, z3);
}

__device__ __forceinline__ void store_z(float* __restrict__ ob, int row, int c0,
                                        int lane, const YR& a, const YR& b,
                                        const YR& c, const float* w)
{
    float z0 = 0.f, z1 = 0.f, z2 = 0.f, z3 = 0.f;
    zrow(a, w[0], w[1], w[2], z0, z1, z2, z3);
    zrow(b, w[3], w[4], w[5], z0, z1, z2, z3);
    zrow(c, w[6], w[7], w[8], z0, z1, z2, z3);
    *(float4*)(ob + (size_t)row * IMG_W + c0 + 4 * lane) =
        make_float4(z0, z1, z2, z3);
}

__global__ __launch_bounds__(WARPS_PER_CTA * 32)
void conv2x_stream(const float* __restrict__ x, const float* __restrict__ w1g,
                   const float* __restrict__ w2g, float* __restrict__ out)
{
    const int lane  = threadIdx.x & 31;
    const int wrp   = threadIdx.x >> 5;
    const int strip = blockIdx.x;                      // 0..15
    const int chunk = blockIdx.y * WARPS_PER_CTA + wrp;// 0..31
    const int c0 = strip * 128;
    const int R0 = chunk * ROWS_PER_WARP;
    const bool lE = (strip == 0);
    const bool rE = (strip == STRIPS - 1);
    const bool killE = (lane == 0 && lE) || (lane == 31 && rE);

    const float* xb = x   + (size_t)blockIdx.z * ((size_t)IMG_H * IMG_W);
    float*       ob = out + (size_t)blockIdx.z * ((size_t)IMG_H * IMG_W);

    float w1[9], w2[9];
#pragma unroll
    for (int i = 0; i < 9; i++) { w1[i] = __ldg(w1g + i); w2[i] = __ldg(w2g + i); }

    // Prologue: x rows R0-2..R0+1, y rows R0-1 and R0.
    XR xA = load_xrow(xb, R0 - 2, c0, lane, lE, rE);
    XR xB = load_xrow(xb, R0 - 1, c0, lane, lE, rE);
    XR xC = load_xrow(xb, R0,     c0, lane, lE, rE);
    YR yA = compute_y(xA, xB, xC, w1, (unsigned)(R0 - 1) < IMG_H, lane, killE);
    xA = load_xrow(xb, R0 + 1, c0, lane, lE, rE);
    YR yB = compute_y(xB, xC, xA, w1, true, lane, killE);
    YR yC;

    int r = R0;
    // STEP: load x(r+2), compute y(r+1), emit z(r). Roles rotate with period 3.
#define STEP(X0, X1, X2, Y0, Y1, Y2)                                          \
    do {                                                                      \
        X0 = load_xrow(xb, r + 2, c0, lane, lE, rE);                          \
        Y2 = compute_y(X1, X2, X0, w1, (unsigned)(r + 1) < IMG_H, lane, killE);\
        store_z(ob, r, c0, lane, Y0, Y1, Y2, w2);                             \
        r++;                                                                  \
    } while (0)

#pragma unroll 1
    for (int i = 0; i < ROWS_PER_WARP / 3; i++) {      // 21 triples = 63 rows
        STEP(xB, xC, xA, yA, yB, yC);
        STEP(xC, xA, xB, yB, yC, yA);
        STEP(xA, xB, xC, yC, yA, yB);
    }
    STEP(xB, xC, xA, yA, yB, yC);                      // row 64
#undef STEP
}

extern "C" void kernel_launch(void* const* d_in, const int* in_sizes, int n_in,
                              void* d_out, int out_size)
{
    const float* x  = (const float*)d_in[0];
    const float* w1 = (const float*)d_in[1];
    const float* w2 = (const float*)d_in[2];
    float* out = (float*)d_out;

    const int B = in_sizes[0] / (IMG_H * IMG_W);       // 16
    // grid: 16 strips x 8 chunk-groups (4 warps each) x B images
    dim3 grid(STRIPS, (IMG_H / ROWS_PER_WARP) / WARPS_PER_CTA, B);
    conv2x_stream<<<grid, WARPS_PER_CTA * 32>>>(x, w1, w2, out);
}

// round 5
// speedup vs baseline: 1.7025x; 1.0989x over previous
#include <cuda_runtime.h>

// Fused y = conv3x3_same(x, w1); z = conv3x3_same(y, w2) for [16,1,2048,2048] fp32.
// Register-streaming, no smem/barriers. Each warp owns a 128-col x 64-row chunk,
// lane owns 4 cols. 3-deep software-pipelined row loads (MLP~3 per warp).
// y forced to 0 outside the image (exact two-pass SAME semantics).

#define IMG_H 2048
#define IMG_W 2048
#define ROWS_PER_WARP 64
#define STRIPS 16
#define WARPS_PER_CTA 4

struct RawX { float4 v; float h0, h1; };
struct XR { float v0, v1, v2, v3, xm1, xp4, ea, ec; };
struct YR { float y0, y1, y2, y3, ym1, yp4; };

__device__ __forceinline__ RawX load_raw(const float* __restrict__ xb, int row,
                                         int c0, int lane, bool lE, bool rE)
{
    RawX p; p.v = make_float4(0.f, 0.f, 0.f, 0.f); p.h0 = 0.f; p.h1 = 0.f;
    if ((unsigned)row < IMG_H) {
        const float* base = xb + (size_t)row * IMG_W + c0;
        p.v = __ldg((const float4*)(base + 4 * lane));
        if (lane == 0 && !lE)  { float2 h = __ldg((const float2*)(base - 2));   p.h0 = h.x; p.h1 = h.y; }
        if (lane == 31 && !rE) { float2 h = __ldg((const float2*)(base + 128)); p.h0 = h.x; p.h1 = h.y; }
    }
    return p;
}

__device__ __forceinline__ XR convert(const RawX& p, int lane)
{
    XR r;
    r.v0 = p.v.x; r.v1 = p.v.y; r.v2 = p.v.z; r.v3 = p.v.w;
    float up = __shfl_up_sync(0xffffffffu, p.v.w, 1);
    float dn = __shfl_down_sync(0xffffffffu, p.v.x, 1);
    r.xm1 = (lane == 0)  ? p.h1 : up;     // x[c-1]
    r.xp4 = (lane == 31) ? p.h0 : dn;     // x[c+4]
    r.ea  = (lane == 0)  ? p.h0 : p.v.w;  // edge col inputs
    r.ec  = (lane == 0)  ? p.v.x : p.h1;
    return r;
}

__device__ __forceinline__ void acc3(const XR& r, float wa, float wb, float wc,
                                     float& a0, float& a1, float& a2, float& a3,
                                     float& ae, int lane)
{
    a0 = fmaf(wa, r.xm1, a0); a0 = fmaf(wb, r.v0, a0); a0 = fmaf(wc, r.v1, a0);
    a1 = fmaf(wa, r.v0,  a1); a1 = fmaf(wb, r.v1, a1); a1 = fmaf(wc, r.v2, a1);
    a2 = fmaf(wa, r.v1,  a2); a2 = fmaf(wb, r.v2, a2); a2 = fmaf(wc, r.v3, a2);
    a3 = fmaf(wa, r.v2,  a3); a3 = fmaf(wb, r.v3, a3); a3 = fmaf(wc, r.xp4, a3);
    float eb = (lane == 0) ? r.xm1 : r.xp4;
    ae = fmaf(wa, r.ea, ae); ae = fmaf(wb, eb, ae); ae = fmaf(wc, r.ec, ae);
}

__device__ __forceinline__ YR compute_y(const XR& a, const XR& b, const XR& c,
                                        const float* w, bool valid, int lane,
                                        bool killE)
{
    float y0 = 0.f, y1 = 0.f, y2 = 0.f, y3 = 0.f, ye = 0.f;
    acc3(a, w[0], w[1], w[2], y0, y1, y2, y3, ye, lane);
    acc3(b, w[3], w[4], w[5], y0, y1, y2, y3, ye, lane);
    acc3(c, w[6], w[7], w[8], y0, y1, y2, y3, ye, lane);
    if (!valid) { y0 = y1 = y2 = y3 = ye = 0.f; }   // warp-uniform
    if (killE) ye = 0.f;                            // y zero-pad outside image cols
    YR o; o.y0 = y0; o.y1 = y1; o.y2 = y2; o.y3 = y3;
    float up = __shfl_up_sync(0xffffffffu, y3, 1);
    float dn = __shfl_down_sync(0xffffffffu, y0, 1);
    o.ym1 = (lane == 0)  ? ye : up;
    o.yp4 = (lane == 31) ? ye : dn;
    return o;
}

__device__ __forceinline__ void zrow(const YR& r, float wa, float wb, float wc,
                                     float& z0, float& z1, float& z2, float& z3)
{
    z0 = fmaf(wa, r.ym1, z0); z0 = fmaf(wb, r.y0, z0); z0 = fmaf(wc, r.y1, z0);
    z1 = fmaf(wa, r.y0,  z1); z1 = fmaf(wb, r.y1, z1); z1 = fmaf(wc, r.y2, z1);
    z2 = fmaf(wa, r.y1,  z2); z2 = fmaf(wb, r.y2, z2); z2 = fmaf(wc, r.y3, z2);
    z3 = fmaf(wa, r.y2,  z3); z3 = fmaf(wb, r.y3, z3); z3 = fmaf(wc, r.yp4, z3);
}

__device__ __forceinline__ void store_z(float* __restrict__ ob, int row, int c0,
                                        int lane, const YR& a, const YR& b,
                                        const YR& c, const float* w)
{
    float z0 = 0.f, z1 = 0.f, z2 = 0.f, z3 = 0.f;
    zrow(a, w[0], w[1], w[2], z0, z1, z2, z3);
    zrow(b, w[3], w[4], w[5], z0, z1, z2, z3);
    zrow(c, w[6], w[7], w[8], z0, z1, z2, z3);
    *(float4*)(ob + (size_t)row * IMG_W + c0 + 4 * lane) =
        make_float4(z0, z1, z2, z3);
}

__global__ __launch_bounds__(WARPS_PER_CTA * 32)
void conv2x_stream(const float* __restrict__ x, const float* __restrict__ w1g,
                   const float* __restrict__ w2g, float* __restrict__ out)
{
    const int lane  = threadIdx.x & 31;
    const int wrp   = threadIdx.x >> 5;
    const int strip = blockIdx.x;
    const int chunk = blockIdx.y * WARPS_PER_CTA + wrp;
    const int c0 = strip * 128;
    const int R0 = chunk * ROWS_PER_WARP;
    const bool lE = (strip == 0);
    const bool rE = (strip == STRIPS - 1);
    const bool killE = (lane == 0 && lE) || (lane == 31 && rE);

    const float* xb = x   + (size_t)blockIdx.z * ((size_t)IMG_H * IMG_W);
    float*       ob = out + (size_t)blockIdx.z * ((size_t)IMG_H * IMG_W);

    float w1[9], w2[9];
#pragma unroll
    for (int i = 0; i < 9; i++) { w1[i] = __ldg(w1g + i); w2[i] = __ldg(w2g + i); }

    // ---- Prologue: fill the 3-deep raw queue and the XR/Y pipeline ----
    RawX pA = load_raw(xb, R0 - 2, c0, lane, lE, rE);
    RawX pB = load_raw(xb, R0 - 1, c0, lane, lE, rE);
    RawX pC = load_raw(xb, R0,     c0, lane, lE, rE);

    XR xA = convert(pA, lane);  pA = load_raw(xb, R0 + 1, c0, lane, lE, rE);
    XR xB = convert(pB, lane);  pB = load_raw(xb, R0 + 2, c0, lane, lE, rE);
    XR xC = convert(pC, lane);  pC = load_raw(xb, R0 + 3, c0, lane, lE, rE);

    YR yA = compute_y(xA, xB, xC, w1, R0 > 0, lane, killE);       // y(R0-1)
    xA = convert(pA, lane);     pA = load_raw(xb, R0 + 4, c0, lane, lE, rE);
    YR yB = compute_y(xB, xC, xA, w1, true, lane, killE);         // y(R0)
    YR yC;

    int r = R0;
    // Steady state: convert x(r+2) (loaded 3 steps ago), prefetch x(r+5),
    // compute y(r+1), store z(r).
#define STEP(P, X0, X1, X2, Y0, Y1, Y2)                                        \
    do {                                                                       \
        X0 = convert(P, lane);                                                 \
        P  = load_raw(xb, r + 5, c0, lane, lE, rE);                            \
        Y2 = compute_y(X1, X2, X0, w1, (unsigned)(r + 1) < IMG_H, lane, killE);\
        store_z(ob, r, c0, lane, Y0, Y1, Y2, w2);                              \
        r++;                                                                   \
    } while (0)

#pragma unroll 1
    for (int i = 0; i < 21; i++) {                    // 63 rows
        STEP(pB, xB, xC, xA, yA, yB, yC);
        STEP(pC, xC, xA, xB, yB, yC, yA);
        STEP(pA, xA, xB, xC, yC, yA, yB);
    }
    STEP(pB, xB, xC, xA, yA, yB, yC);                 // row 64
#undef STEP
}

extern "C" void kernel_launch(void* const* d_in, const int* in_sizes, int n_in,
                              void* d_out, int out_size)
{
    const float* x  = (const float*)d_in[0];
    const float* w1 = (const float*)d_in[1];
    const float* w2 = (const float*)d_in[2];
    float* out = (float*)d_out;

    const int B = in_sizes[0] / (IMG_H * IMG_W);      // 16
    dim3 grid(STRIPS, (IMG_H / ROWS_PER_WARP) / WARPS_PER_CTA, B);  // 16 x 8 x 16
    conv2x_stream<<<grid, WARPS_PER_CTA * 32>>>(x, w1, w2, out);
}

// round 6
// speedup vs baseline: 1.8252x; 1.0721x over previous
#include <cuda_runtime.h>

// Fused y = conv3x3_same(x, w1); z = conv3x3_same(y, w2), [16,1,2048,2048] fp32.
// Register-streaming with incremental accumulation and packed f32x2 FMAs.
// Each warp: 128-col strip x 64-row chunk, lane owns 4 cols. Each arriving
// x row updates 2 partial y rows + completes one; each completed y row
// updates 2 partial z rows + completes one -> store. No smem, no barriers.
// y is forced to 0 outside the image (exact two-pass SAME semantics).

#define IMG_H 2048
#define IMG_W 2048
#define STRIPS 16
#define WARPS_PER_CTA 4

typedef unsigned long long u64;

__device__ __forceinline__ u64 pk(float lo, float hi) {
    u64 r; asm("mov.b64 %0, {%1, %2};" : "=l"(r) : "f"(lo), "f"(hi)); return r;
}
__device__ __forceinline__ float lo32(u64 v) { return __uint_as_float((unsigned)v); }
__device__ __forceinline__ float hi32(u64 v) { return __uint_as_float((unsigned)(v >> 32)); }
__device__ __forceinline__ u64 fma2(u64 a, u64 b, u64 c) {
    u64 d; asm("fma.rn.f32x2 %0, %1, %2, %3;" : "=l"(d) : "l"(a), "l"(b), "l"(c)); return d;
}
__device__ __forceinline__ u64 mul2(u64 a, u64 b) {
    u64 d; asm("mul.rn.f32x2 %0, %1, %2;" : "=l"(d) : "l"(a), "l"(b)); return d;
}

struct Raw { float4 v; float2 h; };
struct XP  { u64 P0, P1, P2, P3, P4; float ea, eb, ec; };   // paired x row
struct YA  { u64 a01, a23; float ae; };                     // partial y row
struct YQ  { u64 Q0, Q1, Q2, Q3, Q4; };                     // paired y row
struct ZA  { u64 a01, a23; };                               // partial z row

template <bool SAFE>
__device__ __forceinline__ Raw ldrow(const float*& lp, const float*& hp,
                                     int& lr, bool hOK)
{
    Raw o;
    bool rv = SAFE || ((unsigned)lr < IMG_H);
    if (rv) o.v = __ldg((const float4*)lp);
    else    o.v = make_float4(0.f, 0.f, 0.f, 0.f);
    if (hOK && rv) o.h = __ldg((const float2*)hp);
    else           o.h = make_float2(0.f, 0.f);
    lp += IMG_W; hp += IMG_W;
    if (!SAFE) lr++;
    return o;
}

__device__ __forceinline__ XP cvt(const Raw& p, int lane)
{
    float up = __shfl_up_sync(0xffffffffu, p.v.w, 1);
    float dn = __shfl_down_sync(0xffffffffu, p.v.x, 1);
    float xm1 = (lane == 0)  ? p.h.y : up;   // x[c-1]
    float xp4 = (lane == 31) ? p.h.x : dn;   // x[c+4]
    XP x;
    x.P0 = pk(xm1,   p.v.x);
    x.P1 = pk(p.v.x, p.v.y);
    x.P2 = pk(p.v.y, p.v.z);
    x.P3 = pk(p.v.z, p.v.w);
    x.P4 = pk(p.v.w, xp4);
    x.ea = (lane == 0) ? p.h.x : p.v.w;      // x[edge-1]
    x.eb = (lane == 0) ? xm1   : xp4;        // x[edge]
    x.ec = (lane == 0) ? p.v.x : p.h.y;      // x[edge+1]
    return x;
}

template <int A, bool FIRST>
__device__ __forceinline__ void addY(YA& y, const XP& x, const u64* W)
{
    if (FIRST) {
        y.a01 = mul2(W[3*A], x.P0);
        y.a23 = mul2(W[3*A], x.P2);
        y.ae  = lo32(W[3*A]) * x.ea;
    } else {
        y.a01 = fma2(W[3*A], x.P0, y.a01);
        y.a23 = fma2(W[3*A], x.P2, y.a23);
        y.ae  = fmaf(lo32(W[3*A]), x.ea, y.ae);
    }
    y.a01 = fma2(W[3*A+1], x.P1, y.a01);
    y.a23 = fma2(W[3*A+1], x.P3, y.a23);
    y.ae  = fmaf(lo32(W[3*A+1]), x.eb, y.ae);
    y.a01 = fma2(W[3*A+2], x.P2, y.a01);
    y.a23 = fma2(W[3*A+2], x.P4, y.a23);
    y.ae  = fmaf(lo32(W[3*A+2]), x.ec, y.ae);
}

template <bool SAFE>
__device__ __forceinline__ YQ fin(YA y, bool valid, bool killE, int lane)
{
    if (!SAFE && !valid) { y.a01 = 0ull; y.a23 = 0ull; y.ae = 0.f; }
    if (killE) y.ae = 0.f;
    float y0 = lo32(y.a01), y3 = hi32(y.a23);
    float up = __shfl_up_sync(0xffffffffu, y3, 1);
    float dn = __shfl_down_sync(0xffffffffu, y0, 1);
    float ym1 = (lane == 0)  ? y.ae : up;
    float yp4 = (lane == 31) ? y.ae : dn;
    YQ q;
    q.Q0 = pk(ym1, y0);
    q.Q1 = y.a01;
    q.Q2 = pk(hi32(y.a01), lo32(y.a23));
    q.Q3 = y.a23;
    q.Q4 = pk(y3, yp4);
    return q;
}

template <int A, bool FIRST>
__device__ __forceinline__ void addZ(ZA& z, const YQ& q, const u64* W)
{
    if (FIRST) {
        z.a01 = mul2(W[3*A], q.Q0);
        z.a23 = mul2(W[3*A], q.Q2);
    } else {
        z.a01 = fma2(W[3*A], q.Q0, z.a01);
        z.a23 = fma2(W[3*A], q.Q2, z.a23);
    }
    z.a01 = fma2(W[3*A+1], q.Q1, z.a01);
    z.a23 = fma2(W[3*A+1], q.Q3, z.a23);
    z.a01 = fma2(W[3*A+2], q.Q2, z.a01);
    z.a23 = fma2(W[3*A+2], q.Q4, z.a23);
}

__device__ __forceinline__ void stz(float* p, const ZA& z)
{
    *(float4*)p = make_float4(lo32(z.a01), hi32(z.a01), lo32(z.a23), hi32(z.a23));
}

template <bool SAFE>
__device__ __forceinline__ void run(const float* __restrict__ xb,
                                    float* __restrict__ ob,
                                    const float* __restrict__ w1g,
                                    const float* __restrict__ w2g,
                                    int c0, int R0, int lane, bool lE, bool rE)
{
    u64 W1[9], W2[9];
#pragma unroll
    for (int i = 0; i < 9; i++) {
        float a = __ldg(w1g + i); W1[i] = pk(a, a);
        float b = __ldg(w2g + i); W2[i] = pk(b, b);
    }
    const bool hOK   = (lane == 0 && !lE) || (lane == 31 && !rE);
    const bool killE = (lane == 0 && lE) || (lane == 31 && rE);

    const float* lp = xb + (size_t)(R0 - 2) * IMG_W + c0 + 4 * lane;
    const float* hp = lp + ((lane == 31) ? 4 : -2);
    float*     orow = ob + (size_t)R0 * IMG_W + c0 + 4 * lane;
    int lr = R0 - 2;      // row index for load predication (unsafe only)
    int r  = R0;          // current output row (for y validity, unsafe only)

    // ---- Prologue: rows R0-2 .. R0+4 loaded; y(R0-1), y(R0) completed ----
    Raw q0 = ldrow<SAFE>(lp, hp, lr, hOK);
    Raw q1 = ldrow<SAFE>(lp, hp, lr, hOK);
    Raw q2 = ldrow<SAFE>(lp, hp, lr, hOK);

    YA t1, t2, ya, yb, yc;
    ZA za, zb, zc;

    XP A = cvt(q0, lane); q0 = ldrow<SAFE>(lp, hp, lr, hOK);
    addY<0, true >(t1, A, W1);                       // partial y(R0-1)
    XP B = cvt(q1, lane); q1 = ldrow<SAFE>(lp, hp, lr, hOK);
    addY<1, false>(t1, B, W1);
    addY<0, true >(t2, B, W1);                       // partial y(R0)
    XP C = cvt(q2, lane); q2 = ldrow<SAFE>(lp, hp, lr, hOK);
    addY<2, false>(t1, C, W1);                       // y(R0-1) complete
    addY<1, false>(t2, C, W1);
    addY<0, true >(ya, C, W1);                       // partial y(R0+1)
    YQ Q = fin<SAFE>(t1, (unsigned)(R0 - 1) < IMG_H, killE, lane);
    addZ<0, true >(za, Q, W2);                       // z(R0): w2row0 * y(R0-1)
    XP D = cvt(q0, lane); q0 = ldrow<SAFE>(lp, hp, lr, hOK);
    addY<2, false>(t2, D, W1);                       // y(R0) complete
    addY<1, false>(ya, D, W1);
    addY<0, true >(yb, D, W1);                       // partial y(R0+2)
    Q = fin<SAFE>(t2, true, killE, lane);
    addZ<1, false>(za, Q, W2);                       // z(R0) += w2row1 * y(R0)
    addZ<0, true >(zb, Q, W2);                       // z(R0+1): w2row0 * y(R0)

    // ---- Steady state: 64 steps; step r converts x(r+2), stores z(r) ----
#define STEP(P, Y0, Y1, Y2, Z0, Z1, Z2)                                       \
    do {                                                                      \
        XP X = cvt(P, lane);                                                  \
        P = ldrow<SAFE>(lp, hp, lr, hOK);          /* row r+5 */              \
        addY<2, false>(Y0, X, W1);                 /* y(r+1) complete */      \
        addY<1, false>(Y1, X, W1);                                            \
        addY<0, true >(Y2, X, W1);                 /* new partial y(r+3) */   \
        YQ Qs = fin<SAFE>(Y0, (unsigned)(r + 1) < IMG_H, killE, lane);        \
        addZ<2, false>(Z0, Qs, W2);                /* z(r) complete */        \
        addZ<1, false>(Z1, Qs, W2);                                           \
        addZ<0, true >(Z2, Qs, W2);                /* new partial z(r+2) */   \
        stz(orow, Z0);                                                        \
        orow += IMG_W; r++;                                                   \
    } while (0)

#pragma unroll 1
    for (int i = 0; i < 21; i++) {                  // 63 rows
        STEP(q1, ya, yb, yc, za, zb, zc);
        STEP(q2, yb, yc, ya, zb, zc, za);
        STEP(q0, yc, ya, yb, zc, za, zb);
    }
    STEP(q1, ya, yb, yc, za, zb, zc);               // row 64
#undef STEP
}

__global__ __launch_bounds__(WARPS_PER_CTA * 32, 5)
void conv2x_acc(const float* __restrict__ x, const float* __restrict__ w1g,
                const float* __restrict__ w2g, float* __restrict__ out)
{
    const int lane  = threadIdx.x & 31;
    const int wrp   = threadIdx.x >> 5;
    const int strip = blockIdx.x;
    const int chunk = blockIdx.y * WARPS_PER_CTA + wrp;   // 0..31
    const int c0 = strip * 128;
    const int R0 = chunk * 64;
    const bool lE = (strip == 0);
    const bool rE = (strip == STRIPS - 1);

    const float* xb = x   + (size_t)blockIdx.z * ((size_t)IMG_H * IMG_W);
    float*       ob = out + (size_t)blockIdx.z * ((size_t)IMG_H * IMG_W);

    if (chunk != 0 && chunk != (IMG_H / 64) - 1)
        run<true >(xb, ob, w1g, w2g, c0, R0, lane, lE, rE);
    else
        run<false>(xb, ob, w1g, w2g, c0, R0, lane, lE, rE);
}

extern "C" void kernel_launch(void* const* d_in, const int* in_sizes, int n_in,
                              void* d_out, int out_size)
{
    const float* x  = (const float*)d_in[0];
    const float* w1 = (const float*)d_in[1];
    const float* w2 = (const float*)d_in[2];
    float* out = (float*)d_out;

    const int B = in_sizes[0] / (IMG_H * IMG_W);          // 16
    dim3 grid(STRIPS, (IMG_H / 64) / WARPS_PER_CTA, B);   // 16 x 8 x 16
    conv2x_acc<<<grid, WARPS_PER_CTA * 32>>>(x, w1, w2, out);
}

// round 7
// speedup vs baseline: 1.8977x; 1.0397x over previous
#include <cuda_runtime.h>

// Fused y = conv3x3_same(x, w1); z = conv3x3_same(y, w2), [16,1,2048,2048] fp32.
// Register-streaming, incremental accumulation, packed f32x2 FMAs, 8 cols/lane.
// Warp = 256-col strip x 64-row chunk. Each arriving x row updates 2 partial
// y rows + completes one; each completed y row updates 2 partial z rows +
// completes one -> store. No smem, no barriers. y forced to 0 outside the
// image (exact two-pass SAME semantics).

#define IMG_H 2048
#define IMG_W 2048
#define STRIPS 8          // 2048 / 256
#define WARPS_PER_CTA 4

typedef unsigned long long u64;

__device__ __forceinline__ u64 pk(float lo, float hi) {
    u64 r; asm("mov.b64 %0, {%1, %2};" : "=l"(r) : "f"(lo), "f"(hi)); return r;
}
__device__ __forceinline__ float lo32(u64 v) { return __uint_as_float((unsigned)v); }
__device__ __forceinline__ float hi32(u64 v) { return __uint_as_float((unsigned)(v >> 32)); }
__device__ __forceinline__ u64 fma2(u64 a, u64 b, u64 c) {
    u64 d; asm("fma.rn.f32x2 %0, %1, %2, %3;" : "=l"(d) : "l"(a), "l"(b), "l"(c)); return d;
}
__device__ __forceinline__ u64 mul2(u64 a, u64 b) {
    u64 d; asm("mul.rn.f32x2 %0, %1, %2;" : "=l"(d) : "l"(a), "l"(b)); return d;
}

struct Raw { float4 a, b; float2 h; };
struct XP  { u64 P[9]; float ea, eb, ec; };   // P[k] = (x[k-1], x[k]), x[-1]=xm1, x[8]=xp8
struct YA  { u64 a[4]; float ae; };           // partial y row (pairs) + edge col
struct YQ  { u64 Q[9]; };                     // Q[k] = (y[k-1], y[k])
struct ZA  { u64 a[4]; };                     // partial z row

template <bool SAFE>
__device__ __forceinline__ Raw ldrow(const float*& lp, const float*& hp,
                                     int& lr, bool hOK)
{
    Raw o;
    bool rv = SAFE || ((unsigned)lr < IMG_H);
    if (rv) {
        o.a = __ldg((const float4*)lp);
        o.b = __ldg((const float4*)(lp + 4));
    } else {
        o.a = make_float4(0.f, 0.f, 0.f, 0.f);
        o.b = make_float4(0.f, 0.f, 0.f, 0.f);
    }
    if (hOK && rv) o.h = __ldg((const float2*)hp);
    else           o.h = make_float2(0.f, 0.f);
    lp += IMG_W; hp += IMG_W;
    if (!SAFE) lr++;
    return o;
}

__device__ __forceinline__ XP cvt(const Raw& p, int lane)
{
    float v0 = p.a.x, v1 = p.a.y, v2 = p.a.z, v3 = p.a.w;
    float v4 = p.b.x, v5 = p.b.y, v6 = p.b.z, v7 = p.b.w;
    float up = __shfl_up_sync(0xffffffffu, v7, 1);
    float dn = __shfl_down_sync(0xffffffffu, v0, 1);
    float xm1 = (lane == 0)  ? p.h.y : up;    // x[8g-1]
    float xp8 = (lane == 31) ? p.h.x : dn;    // x[8g+8]
    XP x;
    x.P[0] = pk(xm1, v0); x.P[1] = pk(v0, v1); x.P[2] = pk(v1, v2);
    x.P[3] = pk(v2, v3);  x.P[4] = pk(v3, v4); x.P[5] = pk(v4, v5);
    x.P[6] = pk(v5, v6);  x.P[7] = pk(v6, v7); x.P[8] = pk(v7, xp8);
    x.ea = (lane == 0) ? p.h.x : v7;          // x[edge-1]
    x.eb = (lane == 0) ? xm1   : xp8;         // x[edge]
    x.ec = (lane == 0) ? v0    : p.h.y;       // x[edge+1]
    return x;
}

template <int A, bool FIRST>
__device__ __forceinline__ void addY(YA& y, const XP& x, const u64* W)
{
#pragma unroll
    for (int j = 0; j < 4; j++) {
        u64 t = FIRST ? mul2(W[3*A], x.P[2*j])
                      : fma2(W[3*A], x.P[2*j], y.a[j]);
        t = fma2(W[3*A+1], x.P[2*j+1], t);
        y.a[j] = fma2(W[3*A+2], x.P[2*j+2], t);
    }
    float e = FIRST ? (lo32(W[3*A]) * x.ea)
                    : fmaf(lo32(W[3*A]), x.ea, y.ae);
    e = fmaf(lo32(W[3*A+1]), x.eb, e);
    y.ae = fmaf(lo32(W[3*A+2]), x.ec, e);
}

template <bool SAFE>
__device__ __forceinline__ YQ fin(YA y, bool valid, bool killE, int lane)
{
    if (!SAFE && !valid) {
#pragma unroll
        for (int j = 0; j < 4; j++) y.a[j] = 0ull;
        y.ae = 0.f;
    }
    if (killE) y.ae = 0.f;
    float y0 = lo32(y.a[0]), y7 = hi32(y.a[3]);
    float up = __shfl_up_sync(0xffffffffu, y7, 1);
    float dn = __shfl_down_sync(0xffffffffu, y0, 1);
    float ym1 = (lane == 0)  ? y.ae : up;
    float yp8 = (lane == 31) ? y.ae : dn;
    YQ q;
    q.Q[0] = pk(ym1, y0);
#pragma unroll
    for (int j = 0; j < 4; j++) q.Q[2*j+1] = y.a[j];
#pragma unroll
    for (int j = 1; j < 4; j++) q.Q[2*j] = pk(hi32(y.a[j-1]), lo32(y.a[j]));
    q.Q[8] = pk(y7, yp8);
    return q;
}

template <int A, bool FIRST>
__device__ __forceinline__ void addZ(ZA& z, const YQ& q, const u64* W)
{
#pragma unroll
    for (int j = 0; j < 4; j++) {
        u64 t = FIRST ? mul2(W[3*A], q.Q[2*j])
                      : fma2(W[3*A], q.Q[2*j], z.a[j]);
        t = fma2(W[3*A+1], q.Q[2*j+1], t);
        z.a[j] = fma2(W[3*A+2], q.Q[2*j+2], t);
    }
}

__device__ __forceinline__ void stz(float* p, const ZA& z)
{
    *(float4*)p       = make_float4(lo32(z.a[0]), hi32(z.a[0]),
                                    lo32(z.a[1]), hi32(z.a[1]));
    *(float4*)(p + 4) = make_float4(lo32(z.a[2]), hi32(z.a[2]),
                                    lo32(z.a[3]), hi32(z.a[3]));
}

template <bool SAFE>
__device__ __forceinline__ void run(const float* __restrict__ xb,
                                    float* __restrict__ ob,
                                    const float* __restrict__ w1g,
                                    const float* __restrict__ w2g,
                                    int c0, int R0, int lane, bool lE, bool rE)
{
    u64 W1[9], W2[9];
#pragma unroll
    for (int i = 0; i < 9; i++) {
        float a = __ldg(w1g + i); W1[i] = pk(a, a);
        float b = __ldg(w2g + i); W2[i] = pk(b, b);
    }
    const bool hOK   = (lane == 0 && !lE) || (lane == 31 && !rE);
    const bool killE = (lane == 0 && lE) || (lane == 31 && rE);

    const float* lp = xb + (size_t)(R0 - 2) * IMG_W + c0 + 8 * lane;
    const float* hp = lp + ((lane == 31) ? 8 : -2);
    float*     orow = ob + (size_t)R0 * IMG_W + c0 + 8 * lane;
    int lr = R0 - 2;
    int r  = R0;

    // ---- Prologue: rows R0-2 .. R0+4; y(R0-1), y(R0) completed ----
    Raw q0 = ldrow<SAFE>(lp, hp, lr, hOK);
    Raw q1 = ldrow<SAFE>(lp, hp, lr, hOK);
    Raw q2 = ldrow<SAFE>(lp, hp, lr, hOK);

    YA t1, t2, ya, yb, yc;
    ZA za, zb, zc;

    XP A = cvt(q0, lane); q0 = ldrow<SAFE>(lp, hp, lr, hOK);
    addY<0, true >(t1, A, W1);                        // partial y(R0-1)
    XP B = cvt(q1, lane); q1 = ldrow<SAFE>(lp, hp, lr, hOK);
    addY<1, false>(t1, B, W1);
    addY<0, true >(t2, B, W1);                        // partial y(R0)
    XP C = cvt(q2, lane); q2 = ldrow<SAFE>(lp, hp, lr, hOK);
    addY<2, false>(t1, C, W1);                        // y(R0-1) complete
    addY<1, false>(t2, C, W1);
    addY<0, true >(ya, C, W1);                        // partial y(R0+1)
    YQ Q = fin<SAFE>(t1, (unsigned)(R0 - 1) < IMG_H, killE, lane);
    addZ<0, true >(za, Q, W2);                        // z(R0) : w2row0 * y(R0-1)
    XP D = cvt(q0, lane); q0 = ldrow<SAFE>(lp, hp, lr, hOK);
    addY<2, false>(t2, D, W1);                        // y(R0) complete
    addY<1, false>(ya, D, W1);
    addY<0, true >(yb, D, W1);                        // partial y(R0+2)
    Q = fin<SAFE>(t2, true, killE, lane);
    addZ<1, false>(za, Q, W2);                        // z(R0)   += w2row1 * y(R0)
    addZ<0, true >(zb, Q, W2);                        // z(R0+1) : w2row0 * y(R0)

    // ---- Steady state: step r converts x(r+2), loads x(r+5), stores z(r) ----
#define STEP(P, Y0, Y1, Y2, Z0, Z1, Z2)                                       \
    do {                                                                      \
        XP X = cvt(P, lane);                                                  \
        P = ldrow<SAFE>(lp, hp, lr, hOK);                                     \
        addY<2, false>(Y0, X, W1);                                            \
        addY<1, false>(Y1, X, W1);                                            \
        addY<0, true >(Y2, X, W1);                                            \
        YQ Qs = fin<SAFE>(Y0, (unsigned)(r + 1) < IMG_H, killE, lane);        \
        addZ<2, false>(Z0, Qs, W2);                                           \
        addZ<1, false>(Z1, Qs, W2);                                           \
        addZ<0, true >(Z2, Qs, W2);                                           \
        stz(orow, Z0);                                                        \
        orow += IMG_W; r++;                                                   \
    } while (0)

#pragma unroll 1
    for (int i = 0; i < 21; i++) {                    // 63 rows
        STEP(q1, ya, yb, yc, za, zb, zc);
        STEP(q2, yb, yc, ya, zb, zc, za);
        STEP(q0, yc, ya, yb, zc, za, zb);
    }
    STEP(q1, ya, yb, yc, za, zb, zc);                 // row 64
#undef STEP
}

__global__ __launch_bounds__(WARPS_PER_CTA * 32, 3)
void conv2x_w8(const float* __restrict__ x, const float* __restrict__ w1g,
               const float* __restrict__ w2g, float* __restrict__ out)
{
    const int lane  = threadIdx.x & 31;
    const int wrp   = threadIdx.x >> 5;
    const int strip = blockIdx.x;                      // 0..7
    const int chunk = blockIdx.y * WARPS_PER_CTA + wrp;// 0..31
    const int c0 = strip * 256;
    const int R0 = chunk * 64;
    const bool lE = (strip == 0);
    const bool rE = (strip == STRIPS - 1);

    const float* xb = x   + (size_t)blockIdx.z * ((size_t)IMG_H * IMG_W);
    float*       ob = out + (size_t)blockIdx.z * ((size_t)IMG_H * IMG_W);

    if (chunk != 0 && chunk != (IMG_H / 64) - 1)
        run<true >(xb, ob, w1g, w2g, c0, R0, lane, lE, rE);
    else
        run<false>(xb, ob, w1g, w2g, c0, R0, lane, lE, rE);
}

extern "C" void kernel_launch(void* const* d_in, const int* in_sizes, int n_in,
                              void* d_out, int out_size)
{
    const float* x  = (const float*)d_in[0];
    const float* w1 = (const float*)d_in[1];
    const float* w2 = (const float*)d_in[2];
    float* out = (float*)d_out;

    const int B = in_sizes[0] / (IMG_H * IMG_W);            // 16
    dim3 grid(STRIPS, (IMG_H / 64) / WARPS_PER_CTA, B);     // 8 x 8 x 16
    conv2x_w8<<<grid, WARPS_PER_CTA * 32>>>(x, w1, w2, out);
}